// round 8
// baseline (speedup 1.0000x reference)
#include <cuda_runtime.h>
#include <cuda_bf16.h>
#include <cuda_fp16.h>
#include <cstdint>

// ---------------------------------------------------------------------------
// FactorizedLayer on GB300 (sm_103a) — mma.sync path (base PTX target)
// R8: fp16 (e5m10) hi/lo split. S = Xh*Bh (f32-acc HMMA, half-rate) +
//     [Xh*Bl + Xl*Bh] (f16-acc HMMA, full-rate). Cross terms are ~2^-11 of S
//     so f16 accumulation error is negligible. Aux GEMM shrinks to K=1024
//     (single-digit fp16 suffices for x*W and x^2*G).
// ---------------------------------------------------------------------------

#define DB 4096
#define DN 512
#define DH 1024
#define DL 8
#define RM (DH*DL)

__device__ __align__(16) __half g_Xm[(size_t)DB * 1024];  // [Xh32|Xl32] x16
__device__ __align__(16) __half g_Bm[(size_t)RM * 1024];  // [Bh32|Bl32] x16
__device__ __align__(16) __half g_Aa[(size_t)DB * 1024];  // [Xh512|X2_512]
__device__ __align__(16) __half g_Ba[(size_t)DH * 1024];  // [Wh512|G512]

// ------------------------------- prep kernels ------------------------------

__global__ void prep_A(const float* __restrict__ x) {
    int i = blockIdx.x * 256 + threadIdx.x;          // over 4096*512
    int m = i >> 9, n = i & 511;
    float v = x[i];
    __half h = __float2half(v);
    __half l = __float2half(v - __half2float(h));
    size_t bm = (size_t)m * 1024 + (size_t)(n >> 5) * 64 + (n & 31);
    g_Xm[bm] = h; g_Xm[bm + 32] = l;
    size_t ba = (size_t)m * 1024;
    g_Aa[ba + n] = h;
    g_Aa[ba + 512 + n] = __float2half(v * v);
}

__global__ void prep_Bm(const float* __restrict__ beta) {
    int i = blockIdx.x * 256 + threadIdx.x;          // over 8192*512
    int r = i >> 9, n = i & 511;
    float v = beta[i];
    __half h = __float2half(v);
    __half l = __float2half(v - __half2float(h));
    size_t b = (size_t)r * 1024 + (size_t)(n >> 5) * 64 + (n & 31);
    g_Bm[b] = h; g_Bm[b + 32] = l;
}

__global__ void prep_Ba(const float* __restrict__ beta, const float* __restrict__ W) {
    int i = blockIdx.x * 256 + threadIdx.x;          // over 1024*512
    int hh = i >> 9, n = i & 511;
    float w = W[i];
    const float* bp = beta + (size_t)hh * (DL * DN) + n;
    float g = 0.f;
#pragma unroll
    for (int l = 0; l < DL; l++) { float t = bp[l * DN]; g += t * t; }
    g *= -0.5f;
    size_t b = (size_t)hh * 1024;
    g_Ba[b + n] = __float2half(w);
    g_Ba[b + 512 + n] = __float2half(g);
}

// ------------------------------- common -----------------------------------

__device__ __forceinline__ uint32_t swz(uint32_t o) { return o ^ ((o >> 3) & 0x70); }

constexpr int STAGES = 3;
constexpr int TILEB = 16384;
constexpr int SMEMB = STAGES * TILEB * 2;    // 98304 -> 2 CTAs/SM

#define LDSM_X4(r, a)                                                           \
    asm volatile("ldmatrix.sync.aligned.m8n8.x4.shared.b16 {%0,%1,%2,%3}, [%4];"\
        : "=r"((r)[0]), "=r"((r)[1]), "=r"((r)[2]), "=r"((r)[3]) : "r"(a))

// fp16 inputs, fp32 accumulators
#define MMA16816F(c, a, b0, b1)                                                 \
    asm volatile("mma.sync.aligned.m16n8k16.row.col.f32.f16.f16.f32 "           \
        "{%0,%1,%2,%3}, {%4,%5,%6,%7}, {%8,%9}, {%0,%1,%2,%3};"                 \
        : "+f"((c)[0]), "+f"((c)[1]), "+f"((c)[2]), "+f"((c)[3])                 \
        : "r"((a)[0]), "r"((a)[1]), "r"((a)[2]), "r"((a)[3]), "r"(b0), "r"(b1))

// fp16 inputs, fp16 accumulators (2 c/d regs, f16x2 packed)
#define MMA16816H(c, a, b0, b1)                                                 \
    asm volatile("mma.sync.aligned.m16n8k16.row.col.f16.f16.f16.f16 "           \
        "{%0,%1}, {%2,%3,%4,%5}, {%6,%7}, {%0,%1};"                             \
        : "+r"((c)[0]), "+r"((c)[1])                                             \
        : "r"((a)[0]), "r"((a)[1]), "r"((a)[2]), "r"((a)[3]), "r"(b0), "r"(b1))

// ------------------------------- main GEMM ---------------------------------
// A: g_Xm (4096 x 1024 f16), B: g_Bm (8192 x 1024 f16); per 128B row-chunk:
// [0,64)B = hi half (32 k), [64,128)B = lo half.
// P1 = Xh*Bh in f32 acc; P2 = Xh*Bl, P3 = Xl*Bh in f16 acc (cross terms).

__global__ void __launch_bounds__(128, 2)
fm_main(const __half* __restrict__ gA, const __half* __restrict__ gB,
        float* __restrict__ out)
{
    extern __shared__ __align__(128) char smem[];
    const uint32_t sb = (uint32_t)__cvta_generic_to_shared(smem);
    const int tid = threadIdx.x, lane = tid & 31, wid = tid >> 5;
    const int cm = blockIdx.y * 128, cn = blockIdx.x * 128;
    const int wm = (wid & 1) * 64, wn = (wid >> 1) * 64;
    constexpr int Kld = 1024, KT = 16;

    const int lrow = tid >> 3;
    const int lchunk = tid & 7;
    const __half* gArow = gA + (size_t)(cm + lrow) * Kld + lchunk * 8;
    const __half* gBrow = gB + (size_t)(cn + lrow) * Kld + lchunk * 8;

    const int a_row = wm + (lane & 15);
    const int a_ko  = ((lane >> 4) & 1) * 16;
    const int b_mi  = lane >> 3;
    const int b_row = wn + ((b_mi >> 1) & 1) * 8 + (lane & 7);
    const int b_ko  = (b_mi & 1) * 16;

    float acc[4][8][4];
    uint32_t acch[4][8][2];
#pragma unroll
    for (int i = 0; i < 4; i++)
#pragma unroll
        for (int j = 0; j < 8; j++) {
#pragma unroll
            for (int q = 0; q < 4; q++) acc[i][j][q] = 0.f;
            acch[i][j][0] = 0u; acch[i][j][1] = 0u;
        }

    auto load_stage = [&](int s, int kt) {
        const uint32_t sa = sb + s * TILEB;
        const uint32_t sB = sb + STAGES * TILEB + s * TILEB;
        const int koff = kt * 64;
#pragma unroll
        for (int i = 0; i < 8; i++) {
            uint32_t da = sa + swz((lrow + i * 16) * 128 + lchunk * 16);
            const void* ga = gArow + (size_t)(i * 16) * Kld + koff;
            asm volatile("cp.async.cg.shared.global [%0], [%1], 16;" :: "r"(da), "l"(ga));
            uint32_t db = sB + swz((lrow + i * 16) * 128 + lchunk * 16);
            const void* gb = gBrow + (size_t)(i * 16) * Kld + koff;
            asm volatile("cp.async.cg.shared.global [%0], [%1], 16;" :: "r"(db), "l"(gb));
        }
    };

    auto compute = [&](int s) {
        const uint32_t sa = sb + s * TILEB;
        const uint32_t sB = sb + STAGES * TILEB + s * TILEB;
#pragma unroll
        for (int ks = 0; ks < 2; ks++) {
            uint32_t ah[4][4];
#pragma unroll
            for (int mt = 0; mt < 4; mt++)
                LDSM_X4(ah[mt], sa + swz((a_row + mt * 16) * 128 + ks * 32 + a_ko));
            uint32_t bh[4][4];
#pragma unroll
            for (int jj = 0; jj < 4; jj++)
                LDSM_X4(bh[jj], sB + swz((b_row + jj * 16) * 128 + ks * 32 + b_ko));
            // P1: Xh * Bh (f32 acc)
#pragma unroll
            for (int mt = 0; mt < 4; mt++)
#pragma unroll
                for (int nt = 0; nt < 8; nt++)
                    MMA16816F(acc[mt][nt], ah[mt], bh[nt >> 1][(nt & 1) * 2], bh[nt >> 1][(nt & 1) * 2 + 1]);
            // P2: Xh * Bl (f16 acc), bl streamed per-jj
#pragma unroll
            for (int jj = 0; jj < 4; jj++) {
                uint32_t bl[4];
                LDSM_X4(bl, sB + swz((b_row + jj * 16) * 128 + 64 + ks * 32 + b_ko));
#pragma unroll
                for (int mt = 0; mt < 4; mt++) {
                    MMA16816H(acch[mt][jj * 2 + 0], ah[mt], bl[0], bl[1]);
                    MMA16816H(acch[mt][jj * 2 + 1], ah[mt], bl[2], bl[3]);
                }
            }
            // P3: Xl * Bh (f16 acc), al streamed per-mt
#pragma unroll
            for (int mt = 0; mt < 4; mt++) {
                uint32_t al[4];
                LDSM_X4(al, sa + swz((a_row + mt * 16) * 128 + 64 + ks * 32 + a_ko));
#pragma unroll
                for (int nt = 0; nt < 8; nt++)
                    MMA16816H(acch[mt][nt], al, bh[nt >> 1][(nt & 1) * 2], bh[nt >> 1][(nt & 1) * 2 + 1]);
            }
        }
    };

    load_stage(0, 0);
    asm volatile("cp.async.commit_group;" ::: "memory");
    load_stage(1, 1);
    asm volatile("cp.async.commit_group;" ::: "memory");

    for (int kt = 0; kt < KT; kt++) {
        asm volatile("cp.async.wait_group 1;" ::: "memory");
        __syncthreads();
        if (kt + 2 < KT) load_stage((kt + 2) % STAGES, kt + 2);
        asm volatile("cp.async.commit_group;" ::: "memory");
        compute(kt % STAGES);
    }

    // epilogue: s = P1 + cross; out[row,h] += 0.5 * sum8(s^2)
#pragma unroll
    for (int mt = 0; mt < 4; mt++) {
        const int row  = cm + wm + mt * 16 + (lane >> 2);
        const int row2 = row + 8;
#pragma unroll
        for (int nt = 0; nt < 8; nt++) {
            float2 c01 = __half22float2(*reinterpret_cast<__half2*>(&acch[mt][nt][0]));
            float2 c23 = __half22float2(*reinterpret_cast<__half2*>(&acch[mt][nt][1]));
            float v0 = acc[mt][nt][0] + c01.x;
            float v1 = acc[mt][nt][1] + c01.y;
            float v2 = acc[mt][nt][2] + c23.x;
            float v3 = acc[mt][nt][3] + c23.y;
            float s0 = v0 * v0 + v1 * v1;
            float s1 = v2 * v2 + v3 * v3;
            s0 += __shfl_xor_sync(0xffffffffu, s0, 1);
            s0 += __shfl_xor_sync(0xffffffffu, s0, 2);
            s1 += __shfl_xor_sync(0xffffffffu, s1, 1);
            s1 += __shfl_xor_sync(0xffffffffu, s1, 2);
            if ((lane & 3) == 0) {
                const int h = (cn + wn) / 8 + nt;
                out[(size_t)row  * DH + h] += 0.5f * s0;
                out[(size_t)row2 * DH + h] += 0.5f * s1;
            }
        }
    }
}

// ------------------------------- aux GEMM ----------------------------------
// K=1024: out = [Xh|X2] . [Wh|G]^T + bias  (f16 inputs, f32 acc)

__global__ void __launch_bounds__(128, 2)
fm_aux(const __half* __restrict__ gA, const __half* __restrict__ gB,
       float* __restrict__ out, const float* __restrict__ bias)
{
    extern __shared__ __align__(128) char smem[];
    const uint32_t sb = (uint32_t)__cvta_generic_to_shared(smem);
    const int tid = threadIdx.x, lane = tid & 31, wid = tid >> 5;
    const int cm = blockIdx.y * 128, cn = blockIdx.x * 128;
    const int wm = (wid & 1) * 64, wn = (wid >> 1) * 64;
    constexpr int Kld = 1024, KT = 16;

    const int lrow = tid >> 3;
    const int lchunk = tid & 7;
    const __half* gArow = gA + (size_t)(cm + lrow) * Kld + lchunk * 8;
    const __half* gBrow = gB + (size_t)(cn + lrow) * Kld + lchunk * 8;

    const int a_row = wm + (lane & 15);
    const int a_ko  = ((lane >> 4) & 1) * 16;
    const int b_mi  = lane >> 3;
    const int b_row = wn + ((b_mi >> 1) & 1) * 8 + (lane & 7);
    const int b_ko  = (b_mi & 1) * 16;

    float acc[4][8][4];
#pragma unroll
    for (int i = 0; i < 4; i++)
#pragma unroll
        for (int j = 0; j < 8; j++)
#pragma unroll
            for (int q = 0; q < 4; q++) acc[i][j][q] = 0.f;

    auto load_stage = [&](int s, int kt) {
        const uint32_t sa = sb + s * TILEB;
        const uint32_t sB = sb + STAGES * TILEB + s * TILEB;
        const int koff = kt * 64;
#pragma unroll
        for (int i = 0; i < 8; i++) {
            uint32_t da = sa + swz((lrow + i * 16) * 128 + lchunk * 16);
            const void* ga = gArow + (size_t)(i * 16) * Kld + koff;
            asm volatile("cp.async.cg.shared.global [%0], [%1], 16;" :: "r"(da), "l"(ga));
            uint32_t db = sB + swz((lrow + i * 16) * 128 + lchunk * 16);
            const void* gb = gBrow + (size_t)(i * 16) * Kld + koff;
            asm volatile("cp.async.cg.shared.global [%0], [%1], 16;" :: "r"(db), "l"(gb));
        }
    };

    auto compute = [&](int s) {
        const uint32_t sa = sb + s * TILEB;
        const uint32_t sB = sb + STAGES * TILEB + s * TILEB;
#pragma unroll
        for (int ks = 0; ks < 4; ks++) {
            uint32_t a[4][4];
#pragma unroll
            for (int mt = 0; mt < 4; mt++)
                LDSM_X4(a[mt], sa + swz((a_row + mt * 16) * 128 + ks * 32 + a_ko));
            uint32_t b[4][4];
#pragma unroll
            for (int jj = 0; jj < 4; jj++)
                LDSM_X4(b[jj], sB + swz((b_row + jj * 16) * 128 + ks * 32 + b_ko));
#pragma unroll
            for (int mt = 0; mt < 4; mt++)
#pragma unroll
                for (int nt = 0; nt < 8; nt++)
                    MMA16816F(acc[mt][nt], a[mt], b[nt >> 1][(nt & 1) * 2], b[nt >> 1][(nt & 1) * 2 + 1]);
        }
    };

    load_stage(0, 0);
    asm volatile("cp.async.commit_group;" ::: "memory");
    load_stage(1, 1);
    asm volatile("cp.async.commit_group;" ::: "memory");

    for (int kt = 0; kt < KT; kt++) {
        asm volatile("cp.async.wait_group 1;" ::: "memory");
        __syncthreads();
        if (kt + 2 < KT) load_stage((kt + 2) % STAGES, kt + 2);
        asm volatile("cp.async.commit_group;" ::: "memory");
        compute(kt % STAGES);
    }

#pragma unroll
    for (int mt = 0; mt < 4; mt++) {
        const int row  = cm + wm + mt * 16 + (lane >> 2);
        const int row2 = row + 8;
#pragma unroll
        for (int nt = 0; nt < 8; nt++) {
            const int col = cn + wn + nt * 8 + (lane & 3) * 2;
            float2 bb = *(const float2*)(bias + col);
            float2 v0 = { acc[mt][nt][0] + bb.x, acc[mt][nt][1] + bb.y };
            float2 v1 = { acc[mt][nt][2] + bb.x, acc[mt][nt][3] + bb.y };
            *(float2*)(out + (size_t)row  * DH + col) = v0;
            *(float2*)(out + (size_t)row2 * DH + col) = v1;
        }
    }
}

// --------------------------------- host side --------------------------------

extern "C" void kernel_launch(void* const* d_in, const int* in_sizes, int n_in,
                              void* d_out, int out_size) {
    const float* x    = (const float*)d_in[0];
    const float* beta = (const float*)d_in[1];
    const float* W    = (const float*)d_in[2];
    const float* bias = (const float*)d_in[3];
    float* out = (float*)d_out;
    (void)in_sizes; (void)n_in; (void)out_size;

    void *pXm, *pBm, *pAa, *pBa;
    cudaGetSymbolAddress(&pXm, g_Xm);
    cudaGetSymbolAddress(&pBm, g_Bm);
    cudaGetSymbolAddress(&pAa, g_Aa);
    cudaGetSymbolAddress(&pBa, g_Ba);

    cudaFuncSetAttribute((const void*)fm_main,
                         cudaFuncAttributeMaxDynamicSharedMemorySize, SMEMB);
    cudaFuncSetAttribute((const void*)fm_aux,
                         cudaFuncAttributeMaxDynamicSharedMemorySize, SMEMB);

    prep_A <<<(DB * DN) / 256, 256>>>(x);
    prep_Bm<<<(RM * DN) / 256, 256>>>(beta);
    prep_Ba<<<(DH * DN) / 256, 256>>>(beta, W);

    // aux first: writes every out element (= linear + bias - 0.5*ssq)
    fm_aux<<<dim3(DH / 128, DB / 128), 128, SMEMB>>>(
        (const __half*)pAa, (const __half*)pBa, out, bias);
    // main: read-modify-write adds 0.5 * sum_l s^2
    fm_main<<<dim3(RM / 128, DB / 128), 128, SMEMB>>>(
        (const __half*)pXm, (const __half*)pBm, out);
}